// round 1
// baseline (speedup 1.0000x reference)
#include <cuda_runtime.h>
#include <math.h>

#define NBINS 1001
#define KQ 127
#define HALFB 500
#define EPS_S 1e-4
#define IMIN 63
#define NCAND 438
#define HIST_SUB 4

__device__ unsigned int g_absmax_bits;
__device__ unsigned int g_hist[NBINS];
__device__ double g_kl[NCAND];

// ---------------- init ----------------
__global__ void init_kernel() {
    int t = threadIdx.x;
    if (t == 0) g_absmax_bits = 0u;
    for (int k = t; k < NBINS; k += blockDim.x) g_hist[k] = 0u;
}

// ---------------- absmax ----------------
__global__ void absmax_kernel(const float* __restrict__ x, int n) {
    int n4 = n >> 2;
    const float4* x4 = (const float4*)x;
    float m = 0.f;
    int stride = gridDim.x * blockDim.x;
    for (int idx = blockIdx.x * blockDim.x + threadIdx.x; idx < n4; idx += stride) {
        float4 v = x4[idx];
        m = fmaxf(m, fmaxf(fmaxf(fabsf(v.x), fabsf(v.y)), fmaxf(fabsf(v.z), fabsf(v.w))));
    }
    // tail
    if (blockIdx.x == 0 && threadIdx.x < (n & 3))
        m = fmaxf(m, fabsf(x[n4 * 4 + threadIdx.x]));
    #pragma unroll
    for (int o = 16; o; o >>= 1) m = fmaxf(m, __shfl_xor_sync(0xffffffffu, m, o));
    __shared__ float sm[8];
    int lane = threadIdx.x & 31, w = threadIdx.x >> 5;
    if (lane == 0) sm[w] = m;
    __syncthreads();
    if (w == 0) {
        m = (lane < 8) ? sm[lane] : 0.f;
        #pragma unroll
        for (int o = 4; o; o >>= 1) m = fmaxf(m, __shfl_xor_sync(0xffffffffu, m, o));
        if (lane == 0) atomicMax(&g_absmax_bits, __float_as_uint(m));
    }
}

// ---------------- histogram ----------------
__global__ void hist_kernel(const float* __restrict__ x, int n) {
    __shared__ unsigned int sh[HIST_SUB][NBINS];
    unsigned int* shf = &sh[0][0];
    for (int k = threadIdx.x; k < HIST_SUB * NBINS; k += blockDim.x) shf[k] = 0u;
    __syncthreads();

    float a = __uint_as_float(g_absmax_bits);
    double da = (double)a;
    double inv = (double)NBINS / (2.0 * da);
    float step = (2.0f * a) / (float)NBINS;   // fp32 linspace step emulation
    unsigned int* hsub = sh[(threadIdx.x >> 5) & (HIST_SUB - 1)];

    int n4 = n >> 2;
    const float4* x4 = (const float4*)x;
    int stride = gridDim.x * blockDim.x;
    for (int idx = blockIdx.x * blockDim.x + threadIdx.x; idx < n4; idx += stride) {
        float4 v = x4[idx];
        float c[4] = {v.x, v.y, v.z, v.w};
        #pragma unroll
        for (int j = 0; j < 4; j++) {
            double vd = (double)c[j];
            int b = (int)((vd + da) * inv);
            // refine against fp32 edges (edge_k = k*step + (-a)), searchsorted 'right' semantics
            float e0 = __fadd_rn(__fmul_rn((float)b, step), -a);
            if (c[j] < e0) b -= 1;
            else {
                float e1 = __fadd_rn(__fmul_rn((float)(b + 1), step), -a);
                if (c[j] >= e1) b += 1;
            }
            b = max(0, min(NBINS - 1, b));
            atomicAdd(&hsub[b], 1u);
        }
    }
    // tail
    if (blockIdx.x == 0 && threadIdx.x < (n & 3)) {
        float c = x[n4 * 4 + threadIdx.x];
        double vd = (double)c;
        int b = (int)((vd + da) * inv);
        float e0 = __fadd_rn(__fmul_rn((float)b, step), -a);
        if (c < e0) b -= 1;
        else {
            float e1 = __fadd_rn(__fmul_rn((float)(b + 1), step), -a);
            if (c >= e1) b += 1;
        }
        b = max(0, min(NBINS - 1, b));
        atomicAdd(&hsub[b], 1u);
    }
    __syncthreads();
    for (int k = threadIdx.x; k < NBINS; k += blockDim.x) {
        unsigned int s = 0;
        #pragma unroll
        for (int j = 0; j < HIST_SUB; j++) s += sh[j][k];
        if (s) atomicAdd(&g_hist[k], s);
    }
}

// ---------------- reductions ----------------
__device__ __forceinline__ double warpSumD(double v) {
    #pragma unroll
    for (int o = 16; o; o >>= 1) v += __shfl_xor_sync(0xffffffffu, v, o);
    return v;
}
__device__ __forceinline__ double warpMaxD(double v) {
    #pragma unroll
    for (int o = 16; o; o >>= 1) v = fmax(v, __shfl_xor_sync(0xffffffffu, v, o));
    return v;
}
__device__ __forceinline__ double blockSumD(double v, double* sh) {
    int lane = threadIdx.x & 31, w = threadIdx.x >> 5;
    v = warpSumD(v);
    if (lane == 0) sh[w] = v;
    __syncthreads();
    if (w == 0) {
        double t = (lane < 8) ? sh[lane] : 0.0;
        t = warpSumD(t);
        if (lane == 0) sh[0] = t;
    }
    __syncthreads();
    double r = sh[0];
    __syncthreads();
    return r;
}
__device__ __forceinline__ double blockMaxD(double v, double* sh) {
    int lane = threadIdx.x & 31, w = threadIdx.x >> 5;
    v = warpMaxD(v);
    if (lane == 0) sh[w] = v;
    __syncthreads();
    if (w == 0) {
        double t = (lane < 8) ? sh[lane] : -1e300;
        t = warpMaxD(t);
        if (lane == 0) sh[0] = t;
    }
    __syncthreads();
    double r = sh[0];
    __syncthreads();
    return r;
}

// ---------------- per-candidate KL ----------------
__global__ void kl_kernel() {
    const int i = IMIN + (int)blockIdx.x;
    const int L = 2 * i + 1;
    const int start = HALFB - i;
    const int stop = HALFB + i + 1;
    const int m = L / KQ;

    __shared__ float s_h[NBINS];
    __shared__ double s_qb[KQ];
    __shared__ int s_nm[KQ];
    __shared__ double s_red[8];

    for (int k = threadIdx.x; k < NBINS; k += blockDim.x) s_h[k] = (float)g_hist[k];
    for (int k = threadIdx.x; k < KQ; k += blockDim.x) { s_qb[k] = 0.0; s_nm[k] = 0; }
    __syncthreads();

    // left/right outside-range mass (exclusive prefix sums in the reference)
    double ls = 0.0, rs = 0.0;
    for (int k = threadIdx.x; k < NBINS; k += blockDim.x) {
        double v = (double)s_h[k];
        if (k < start) ls += v;
        else if (k >= stop) rs += v;
    }
    double left = blockSumD(ls, s_red);
    double right = blockSumD(rs, s_red);

    // merged-bin sums and nonzero counts
    for (int k = threadIdx.x; k < L; k += blockDim.x) {
        float v = s_h[start + k];
        if (v != 0.f) {
            int seg = min(k / m, KQ - 1);
            atomicAdd(&s_qb[seg], (double)v);
            if (k != L - 1) atomicAdd(&s_nm[seg], 1);
        }
    }
    __syncthreads();

    // per-thread p/q "logits" (uniform smoothing shift cancels in lp/lq; drop it)
    double plog[4], qlog[4];
    double mp = -1e300, mq = -1e300;
    int cnz = 0;
    #pragma unroll
    for (int t = 0; t < 4; t++) {
        int k = threadIdx.x + t * 256;
        if (k < L) {
            double v = (double)s_h[start + k];
            double p = v;
            if (k == 0) p += left;
            if (k == L - 1) p += right;
            double pl = (p == 0.0) ? EPS_S : p;
            int seg = min(k / m, KQ - 1);
            double q = 0.0;
            if (v != 0.0 && k != L - 1 && s_nm[seg] > 0)
                q = s_qb[seg] / (double)s_nm[seg];
            double ql = (q == 0.0) ? EPS_S : q;
            plog[t] = pl; qlog[t] = ql;
            mp = fmax(mp, pl); mq = fmax(mq, ql);
            cnz += (q != 0.0);
        } else {
            plog[t] = -1e300; qlog[t] = -1e300;
        }
    }
    mp = blockMaxD(mp, s_red);
    mq = blockMaxD(mq, s_red);
    double nnz = blockSumD((double)cnz, s_red);

    double sp = 0.0, sq = 0.0;
    #pragma unroll
    for (int t = 0; t < 4; t++) { sp += exp(plog[t] - mp); sq += exp(qlog[t] - mq); }
    sp = blockSumD(sp, s_red);
    sq = blockSumD(sq, s_red);
    double lZp = mp + log(sp);
    double lZq = mq + log(sq);

    double kl = 0.0;
    #pragma unroll
    for (int t = 0; t < 4; t++) {
        double lp = plog[t] - lZp;
        double lq = qlog[t] - lZq;
        kl += exp(lp) * (lp - lq);
    }
    kl = blockSumD(kl, s_red);
    if (threadIdx.x == 0)
        g_kl[blockIdx.x] = (nnz > 0.0) ? kl : (double)INFINITY;
}

// ---------------- argmin + threshold ----------------
__global__ void argmin_kernel(float* __restrict__ out) {
    __shared__ double sv[256];
    __shared__ int si[256];
    double best = (double)INFINITY;
    int bi = 0x7fffffff;
    for (int k = threadIdx.x; k < NCAND; k += blockDim.x) {
        double v = g_kl[k];
        if (v < best || (v == best && k < bi)) { best = v; bi = k; }
    }
    sv[threadIdx.x] = best; si[threadIdx.x] = bi;
    __syncthreads();
    for (int s = 128; s > 0; s >>= 1) {
        if (threadIdx.x < s) {
            double vo = sv[threadIdx.x + s];
            int io = si[threadIdx.x + s];
            if (vo < sv[threadIdx.x] || (vo == sv[threadIdx.x] && io < si[threadIdx.x])) {
                sv[threadIdx.x] = vo; si[threadIdx.x] = io;
            }
        }
        __syncthreads();
    }
    if (threadIdx.x == 0) {
        int i = IMIN + si[0];
        float a = __uint_as_float(g_absmax_bits);
        double thr = -(double)a + 2.0 * (double)a * (double)(i + HALFB + 1) / (double)NBINS;
        out[0] = (float)thr;
    }
}

extern "C" void kernel_launch(void* const* d_in, const int* in_sizes, int n_in,
                              void* d_out, int out_size) {
    const float* x = (const float*)d_in[0];
    int n = in_sizes[0];
    init_kernel<<<1, 1024>>>();
    absmax_kernel<<<1024, 256>>>(x, n);
    hist_kernel<<<1184, 256>>>(x, n);
    kl_kernel<<<NCAND, 256>>>();
    argmin_kernel<<<1, 256>>>((float*)d_out);
}

// round 2
// speedup vs baseline: 3.7375x; 3.7375x over previous
#include <cuda_runtime.h>
#include <math.h>

#define NBINS 1001
#define KQ 127
#define HALFB 500
#define EPS_S 1e-4
#define IMIN 63
#define NCAND 438
#define HIST_SUB 4
#define EXP_CUT -700.0

__device__ unsigned int g_absmax_bits;
__device__ unsigned int g_hist[NBINS];
__device__ double g_kl[NCAND];

// ---------------- init ----------------
__global__ void init_kernel() {
    int t = threadIdx.x;
    if (t == 0) g_absmax_bits = 0u;
    for (int k = t; k < NBINS; k += blockDim.x) g_hist[k] = 0u;
}

// ---------------- absmax ----------------
__global__ void absmax_kernel(const float* __restrict__ x, int n) {
    int n4 = n >> 2;
    const float4* x4 = (const float4*)x;
    float m = 0.f;
    int stride = gridDim.x * blockDim.x;
    for (int idx = blockIdx.x * blockDim.x + threadIdx.x; idx < n4; idx += stride) {
        float4 v = x4[idx];
        m = fmaxf(m, fmaxf(fmaxf(fabsf(v.x), fabsf(v.y)), fmaxf(fabsf(v.z), fabsf(v.w))));
    }
    if (blockIdx.x == 0 && threadIdx.x < (n & 3))
        m = fmaxf(m, fabsf(x[n4 * 4 + threadIdx.x]));
    #pragma unroll
    for (int o = 16; o; o >>= 1) m = fmaxf(m, __shfl_xor_sync(0xffffffffu, m, o));
    __shared__ float sm[8];
    int lane = threadIdx.x & 31, w = threadIdx.x >> 5;
    if (lane == 0) sm[w] = m;
    __syncthreads();
    if (w == 0) {
        m = (lane < 8) ? sm[lane] : 0.f;
        #pragma unroll
        for (int o = 4; o; o >>= 1) m = fmaxf(m, __shfl_xor_sync(0xffffffffu, m, o));
        if (lane == 0) atomicMax(&g_absmax_bits, __float_as_uint(m));
    }
}

// ---------------- histogram (pure fp32 binning + edge refinement) ----------------
__device__ __forceinline__ int bin_of(float c, float a, float inv, float step) {
    // initial fp32 estimate (c + a >= 0, truncation == floor)
    int b = (int)(__fmul_rn(__fadd_rn(c, a), inv));
    // refine against exact fp32 linspace edges: edge(k) = k*step + (-a)
    // searchsorted 'right' - 1 semantics: edge(b) <= c < edge(b+1)
    #pragma unroll
    for (int it = 0; it < 3; it++) {
        float e0 = __fadd_rn(__fmul_rn((float)b, step), -a);
        if (c < e0) { b -= 1; continue; }
        float e1 = __fadd_rn(__fmul_rn((float)(b + 1), step), -a);
        if (c >= e1) { b += 1; continue; }
        break;
    }
    return max(0, min(NBINS - 1, b));
}

__global__ void hist_kernel(const float* __restrict__ x, int n) {
    __shared__ unsigned int sh[HIST_SUB][NBINS];
    unsigned int* shf = &sh[0][0];
    for (int k = threadIdx.x; k < HIST_SUB * NBINS; k += blockDim.x) shf[k] = 0u;
    __syncthreads();

    float a = __uint_as_float(g_absmax_bits);
    float step = __fdiv_rn(__fmul_rn(2.0f, a), (float)NBINS);
    float inv = __fdiv_rn((float)NBINS, __fmul_rn(2.0f, a));
    unsigned int* hsub = sh[(threadIdx.x >> 5) & (HIST_SUB - 1)];

    int n4 = n >> 2;
    const float4* x4 = (const float4*)x;
    int stride = gridDim.x * blockDim.x;
    for (int idx = blockIdx.x * blockDim.x + threadIdx.x; idx < n4; idx += stride) {
        float4 v = x4[idx];
        atomicAdd(&hsub[bin_of(v.x, a, inv, step)], 1u);
        atomicAdd(&hsub[bin_of(v.y, a, inv, step)], 1u);
        atomicAdd(&hsub[bin_of(v.z, a, inv, step)], 1u);
        atomicAdd(&hsub[bin_of(v.w, a, inv, step)], 1u);
    }
    if (blockIdx.x == 0 && threadIdx.x < (n & 3)) {
        float c = x[n4 * 4 + threadIdx.x];
        atomicAdd(&hsub[bin_of(c, a, inv, step)], 1u);
    }
    __syncthreads();
    for (int k = threadIdx.x; k < NBINS; k += blockDim.x) {
        unsigned int s = 0;
        #pragma unroll
        for (int j = 0; j < HIST_SUB; j++) s += sh[j][k];
        if (s) atomicAdd(&g_hist[k], s);
    }
}

// ---------------- reductions ----------------
template <typename T>
__device__ __forceinline__ T warpSumT(T v) {
    #pragma unroll
    for (int o = 16; o; o >>= 1) v += __shfl_xor_sync(0xffffffffu, v, o);
    return v;
}
__device__ __forceinline__ unsigned int warpMaxU(unsigned int v) {
    #pragma unroll
    for (int o = 16; o; o >>= 1) v = max(v, __shfl_xor_sync(0xffffffffu, v, o));
    return v;
}
__device__ __forceinline__ double warpMaxD(double v) {
    #pragma unroll
    for (int o = 16; o; o >>= 1) v = fmax(v, __shfl_xor_sync(0xffffffffu, v, o));
    return v;
}

struct RedShared {
    double d[8];
    unsigned long long u[8];
};

__device__ __forceinline__ double blockSumD(double v, RedShared* sh) {
    int lane = threadIdx.x & 31, w = threadIdx.x >> 5;
    v = warpSumT(v);
    if (lane == 0) sh->d[w] = v;
    __syncthreads();
    if (w == 0) {
        double t = (lane < 8) ? sh->d[lane] : 0.0;
        t = warpSumT(t);
        if (lane == 0) sh->d[0] = t;
    }
    __syncthreads();
    double r = sh->d[0];
    __syncthreads();
    return r;
}
__device__ __forceinline__ unsigned long long blockSumU64(unsigned long long v, RedShared* sh) {
    int lane = threadIdx.x & 31, w = threadIdx.x >> 5;
    v = warpSumT(v);
    if (lane == 0) sh->u[w] = v;
    __syncthreads();
    if (w == 0) {
        unsigned long long t = (lane < 8) ? sh->u[lane] : 0ull;
        t = warpSumT(t);
        if (lane == 0) sh->u[0] = t;
    }
    __syncthreads();
    unsigned long long r = sh->u[0];
    __syncthreads();
    return r;
}
__device__ __forceinline__ unsigned int blockMaxU(unsigned int v, RedShared* sh) {
    int lane = threadIdx.x & 31, w = threadIdx.x >> 5;
    v = warpMaxU(v);
    if (lane == 0) sh->u[w] = v;
    __syncthreads();
    if (w == 0) {
        unsigned int t = (lane < 8) ? (unsigned int)sh->u[lane] : 0u;
        t = warpMaxU(t);
        if (lane == 0) sh->u[0] = t;
    }
    __syncthreads();
    unsigned int r = (unsigned int)sh->u[0];
    __syncthreads();
    return r;
}
__device__ __forceinline__ double blockMaxD(double v, RedShared* sh) {
    int lane = threadIdx.x & 31, w = threadIdx.x >> 5;
    v = warpMaxD(v);
    if (lane == 0) sh->d[w] = v;
    __syncthreads();
    if (w == 0) {
        double t = (lane < 8) ? sh->d[lane] : -1e300;
        t = warpMaxD(t);
        if (lane == 0) sh->d[0] = t;
    }
    __syncthreads();
    double r = sh->d[0];
    __syncthreads();
    return r;
}

// ---------------- per-candidate KL ----------------
__global__ void kl_kernel() {
    const int i = IMIN + (int)blockIdx.x;
    const int L = 2 * i + 1;
    const int start = HALFB - i;
    const int stop = HALFB + i + 1;
    const int m = L / KQ;

    __shared__ unsigned int s_h[NBINS];
    __shared__ unsigned int s_qb[KQ];
    __shared__ int s_nm[KQ];
    __shared__ RedShared s_red;

    for (int k = threadIdx.x; k < NBINS; k += blockDim.x) s_h[k] = g_hist[k];
    for (int k = threadIdx.x; k < KQ; k += blockDim.x) { s_qb[k] = 0u; s_nm[k] = 0; }
    __syncthreads();

    // left/right outside-range mass (packed in one 64-bit reduction)
    unsigned long long pk = 0ull;
    for (int k = threadIdx.x; k < NBINS; k += blockDim.x) {
        unsigned long long v = s_h[k];
        if (k < start) pk += (v << 32);
        else if (k >= stop) pk += v;
    }
    pk = blockSumU64(pk, &s_red);
    unsigned int left = (unsigned int)(pk >> 32);
    unsigned int right = (unsigned int)(pk & 0xffffffffull);

    // merged-bin sums (exact integers) and nonzero counts
    for (int k = threadIdx.x; k < L; k += blockDim.x) {
        unsigned int v = s_h[start + k];
        if (v) {
            int seg = min(k / m, KQ - 1);
            atomicAdd(&s_qb[seg], v);
            if (k != L - 1) atomicAdd(&s_nm[seg], 1);
        }
    }
    __syncthreads();

    // per-thread p/q "logits" (uniform smoothing shift cancels in lp/lq)
    double plog[4], qlog[4];
    unsigned int mpi = 0u;
    double mq = -1e300;
    int cnz = 0;
    #pragma unroll
    for (int t = 0; t < 4; t++) {
        int k = threadIdx.x + t * 256;
        if (k < L) {
            unsigned int v = s_h[start + k];
            unsigned int p = v;
            if (k == 0) p += left;
            if (k == L - 1) p += right;
            double pl = p ? (double)p : EPS_S;
            int seg = min(k / m, KQ - 1);
            double q = 0.0;
            if (v && k != L - 1 && s_nm[seg] > 0)
                q = (double)s_qb[seg] / (double)s_nm[seg];
            double ql = (q == 0.0) ? EPS_S : q;
            plog[t] = pl; qlog[t] = ql;
            mpi = max(mpi, p);
            mq = fmax(mq, ql);
            cnz += (q != 0.0);
        } else {
            plog[t] = -1e300; qlog[t] = -1e300;
        }
    }
    mpi = blockMaxU(mpi, &s_red);
    double mp = mpi ? (double)mpi : EPS_S;
    mq = blockMaxD(mq, &s_red);
    int nnz = (int)blockSumU64((unsigned long long)cnz, &s_red);

    // logsumexp with exact-underflow skip: exp(x)==0.0 (or negligible) for x < -700
    double sp = 0.0, sq = 0.0;
    #pragma unroll
    for (int t = 0; t < 4; t++) {
        double dp = plog[t] - mp;
        double dq = qlog[t] - mq;
        if (dp > EXP_CUT) sp += exp(dp);
        if (dq > EXP_CUT) sq += exp(dq);
    }
    sp = blockSumD(sp, &s_red);
    sq = blockSumD(sq, &s_red);
    double lZp = mp + log(sp);
    double lZq = mq + log(sq);

    double kl = 0.0;
    #pragma unroll
    for (int t = 0; t < 4; t++) {
        double lp = plog[t] - lZp;
        if (lp > EXP_CUT) {
            double lq = qlog[t] - lZq;
            kl += exp(lp) * (lp - lq);
        }
    }
    kl = blockSumD(kl, &s_red);
    if (threadIdx.x == 0)
        g_kl[blockIdx.x] = (nnz > 0) ? kl : (double)INFINITY;
}

// ---------------- argmin + threshold ----------------
__global__ void argmin_kernel(float* __restrict__ out) {
    __shared__ double sv[256];
    __shared__ int si[256];
    double best = (double)INFINITY;
    int bi = 0x7fffffff;
    for (int k = threadIdx.x; k < NCAND; k += blockDim.x) {
        double v = g_kl[k];
        if (v < best || (v == best && k < bi)) { best = v; bi = k; }
    }
    sv[threadIdx.x] = best; si[threadIdx.x] = bi;
    __syncthreads();
    for (int s = 128; s > 0; s >>= 1) {
        if (threadIdx.x < s) {
            double vo = sv[threadIdx.x + s];
            int io = si[threadIdx.x + s];
            if (vo < sv[threadIdx.x] || (vo == sv[threadIdx.x] && io < si[threadIdx.x])) {
                sv[threadIdx.x] = vo; si[threadIdx.x] = io;
            }
        }
        __syncthreads();
    }
    if (threadIdx.x == 0) {
        int i = IMIN + si[0];
        float a = __uint_as_float(g_absmax_bits);
        double thr = -(double)a + 2.0 * (double)a * (double)(i + HALFB + 1) / (double)NBINS;
        out[0] = (float)thr;
    }
}

extern "C" void kernel_launch(void* const* d_in, const int* in_sizes, int n_in,
                              void* d_out, int out_size) {
    const float* x = (const float*)d_in[0];
    int n = in_sizes[0];
    init_kernel<<<1, 1024>>>();
    absmax_kernel<<<1024, 256>>>(x, n);
    hist_kernel<<<1184, 256>>>(x, n);
    kl_kernel<<<NCAND, 256>>>();
    argmin_kernel<<<1, 256>>>((float*)d_out);
}

// round 4
// speedup vs baseline: 4.0950x; 1.0956x over previous
#include <cuda_runtime.h>
#include <math.h>

#define NBINS 1001
#define KQ 127
#define HALFB 500
#define EPS_S 1e-4
#define IMIN 63
#define NCAND 438
#define HIST_SUB 4
#define EXP_CUT -700.0

__device__ unsigned int g_absmax_bits;
__device__ unsigned int g_hist[NBINS];
__device__ double g_kl[NCAND];

// ---------------- init ----------------
__global__ void init_kernel() {
    int t = threadIdx.x;
    if (t == 0) g_absmax_bits = 0u;
    for (int k = t; k < NBINS; k += blockDim.x) g_hist[k] = 0u;
}

// ---------------- absmax ----------------
__global__ void absmax_kernel(const float* __restrict__ x, int n) {
    int n4 = n >> 2;
    const float4* x4 = (const float4*)x;
    float m = 0.f;
    int stride = gridDim.x * blockDim.x;
    for (int idx = blockIdx.x * blockDim.x + threadIdx.x; idx < n4; idx += stride) {
        float4 v = x4[idx];
        m = fmaxf(m, fmaxf(fmaxf(fabsf(v.x), fabsf(v.y)), fmaxf(fabsf(v.z), fabsf(v.w))));
    }
    if (blockIdx.x == 0 && threadIdx.x < (n & 3))
        m = fmaxf(m, fabsf(x[n4 * 4 + threadIdx.x]));
    #pragma unroll
    for (int o = 16; o; o >>= 1) m = fmaxf(m, __shfl_xor_sync(0xffffffffu, m, o));
    __shared__ float sm[8];
    int lane = threadIdx.x & 31, w = threadIdx.x >> 5;
    if (lane == 0) sm[w] = m;
    __syncthreads();
    if (w == 0) {
        m = (lane < 8) ? sm[lane] : 0.f;
        #pragma unroll
        for (int o = 4; o; o >>= 1) m = fmaxf(m, __shfl_xor_sync(0xffffffffu, m, o));
        if (lane == 0) atomicMax(&g_absmax_bits, __float_as_uint(m));
    }
}

// ---------------- histogram (pure fp32 binning + edge refinement) ----------------
__device__ __forceinline__ int bin_of(float c, float a, float inv, float step) {
    int b = (int)(__fmul_rn(__fadd_rn(c, a), inv));
    #pragma unroll
    for (int it = 0; it < 3; it++) {
        float e0 = __fadd_rn(__fmul_rn((float)b, step), -a);
        if (c < e0) { b -= 1; continue; }
        float e1 = __fadd_rn(__fmul_rn((float)(b + 1), step), -a);
        if (c >= e1) { b += 1; continue; }
        break;
    }
    return max(0, min(NBINS - 1, b));
}

__global__ void hist_kernel(const float* __restrict__ x, int n) {
    __shared__ unsigned int sh[HIST_SUB][NBINS];
    unsigned int* shf = &sh[0][0];
    for (int k = threadIdx.x; k < HIST_SUB * NBINS; k += blockDim.x) shf[k] = 0u;
    __syncthreads();

    float a = __uint_as_float(g_absmax_bits);
    float step = __fdiv_rn(__fmul_rn(2.0f, a), (float)NBINS);
    float inv = __fdiv_rn((float)NBINS, __fmul_rn(2.0f, a));
    unsigned int* hsub = sh[(threadIdx.x >> 5) & (HIST_SUB - 1)];

    int n4 = n >> 2;
    const float4* x4 = (const float4*)x;
    int stride = gridDim.x * blockDim.x;
    for (int idx = blockIdx.x * blockDim.x + threadIdx.x; idx < n4; idx += stride) {
        float4 v = x4[idx];
        atomicAdd(&hsub[bin_of(v.x, a, inv, step)], 1u);
        atomicAdd(&hsub[bin_of(v.y, a, inv, step)], 1u);
        atomicAdd(&hsub[bin_of(v.z, a, inv, step)], 1u);
        atomicAdd(&hsub[bin_of(v.w, a, inv, step)], 1u);
    }
    if (blockIdx.x == 0 && threadIdx.x < (n & 3)) {
        float c = x[n4 * 4 + threadIdx.x];
        atomicAdd(&hsub[bin_of(c, a, inv, step)], 1u);
    }
    __syncthreads();
    for (int k = threadIdx.x; k < NBINS; k += blockDim.x) {
        unsigned int s = 0;
        #pragma unroll
        for (int j = 0; j < HIST_SUB; j++) s += sh[j][k];
        if (s) atomicAdd(&g_hist[k], s);
    }
}

// ---------------- reductions ----------------
template <typename T>
__device__ __forceinline__ T warpSumT(T v) {
    #pragma unroll
    for (int o = 16; o; o >>= 1) v += __shfl_xor_sync(0xffffffffu, v, o);
    return v;
}
__device__ __forceinline__ unsigned int warpMaxU(unsigned int v) {
    #pragma unroll
    for (int o = 16; o; o >>= 1) v = max(v, __shfl_xor_sync(0xffffffffu, v, o));
    return v;
}
__device__ __forceinline__ double warpMaxD(double v) {
    #pragma unroll
    for (int o = 16; o; o >>= 1) v = fmax(v, __shfl_xor_sync(0xffffffffu, v, o));
    return v;
}

struct RedShared {
    double d[8];
    unsigned long long u[8];
};

__device__ __forceinline__ double blockSumD(double v, RedShared* sh) {
    int lane = threadIdx.x & 31, w = threadIdx.x >> 5;
    v = warpSumT(v);
    if (lane == 0) sh->d[w] = v;
    __syncthreads();
    if (w == 0) {
        double t = (lane < 8) ? sh->d[lane] : 0.0;
        t = warpSumT(t);
        if (lane == 0) sh->d[0] = t;
    }
    __syncthreads();
    double r = sh->d[0];
    __syncthreads();
    return r;
}
__device__ __forceinline__ unsigned long long blockSumU64(unsigned long long v, RedShared* sh) {
    int lane = threadIdx.x & 31, w = threadIdx.x >> 5;
    v = warpSumT(v);
    if (lane == 0) sh->u[w] = v;
    __syncthreads();
    if (w == 0) {
        unsigned long long t = (lane < 8) ? sh->u[lane] : 0ull;
        t = warpSumT(t);
        if (lane == 0) sh->u[0] = t;
    }
    __syncthreads();
    unsigned long long r = sh->u[0];
    __syncthreads();
    return r;
}
__device__ __forceinline__ unsigned int blockMaxU(unsigned int v, RedShared* sh) {
    int lane = threadIdx.x & 31, w = threadIdx.x >> 5;
    v = warpMaxU(v);
    if (lane == 0) sh->u[w] = v;
    __syncthreads();
    if (w == 0) {
        unsigned int t = (lane < 8) ? (unsigned int)sh->u[lane] : 0u;
        t = warpMaxU(t);
        if (lane == 0) sh->u[0] = t;
    }
    __syncthreads();
    unsigned int r = (unsigned int)sh->u[0];
    __syncthreads();
    return r;
}
__device__ __forceinline__ double blockMaxD(double v, RedShared* sh) {
    int lane = threadIdx.x & 31, w = threadIdx.x >> 5;
    v = warpMaxD(v);
    if (lane == 0) sh->d[w] = v;
    __syncthreads();
    if (w == 0) {
        double t = (lane < 8) ? sh->d[lane] : -1e300;
        t = warpMaxD(t);
        if (lane == 0) sh->d[0] = t;
    }
    __syncthreads();
    double r = sh->d[0];
    __syncthreads();
    return r;
}

// ---------------- per-candidate KL (per-segment restructure) ----------------
// KL = sum_k exp(lp_k) * (lp_k - lq_k), with lp = pl - lZp, lq = ql - lZq.
// q takes <=127 distinct values (one per segment), so per-bin fp64
// divides/exps collapse to per-segment work; bins with exp(lp) < e^-700
// contribute < 1e-301 and are skipped exactly.
__global__ void kl_kernel() {
    const int i = IMIN + (int)blockIdx.x;
    const int L = 2 * i + 1;
    const int start = HALFB - i;
    const int stop = HALFB + i + 1;
    const int m = L / KQ;

    __shared__ unsigned int s_h[NBINS];
    __shared__ unsigned int s_qb[KQ];
    __shared__ unsigned int s_nm[KQ];
    __shared__ double s_q[KQ];      // per-segment q value (0 if unassigned)
    __shared__ RedShared s_red;

    for (int k = threadIdx.x; k < NBINS; k += blockDim.x) s_h[k] = g_hist[k];
    for (int k = threadIdx.x; k < KQ; k += blockDim.x) { s_qb[k] = 0u; s_nm[k] = 0u; }
    __syncthreads();

    // left/right outside-range mass (packed u64 reduction)
    unsigned long long pk = 0ull;
    for (int k = threadIdx.x; k < NBINS; k += blockDim.x) {
        unsigned long long v = s_h[k];
        if (k < start) pk += (v << 32);
        else if (k >= stop) pk += v;
    }
    pk = blockSumU64(pk, &s_red);
    const unsigned int left = (unsigned int)(pk >> 32);
    const unsigned int right = (unsigned int)(pk & 0xffffffffull);

    // per-bin integer pass: segment sums + nonzero counts + p values + max p
    unsigned int pv[4];
    unsigned int vv[4];
    unsigned int mpi = 0u;
    #pragma unroll
    for (int t = 0; t < 4; t++) {
        int k = threadIdx.x + t * 256;
        pv[t] = 0u; vv[t] = 0u;
        if (k < L) {
            unsigned int v = s_h[start + k];
            vv[t] = v;
            unsigned int p = v;
            if (k == 0) p += left;
            if (k == L - 1) p += right;
            pv[t] = p;
            mpi = max(mpi, p);
            if (v) {
                int seg = min(k / m, KQ - 1);
                atomicAdd(&s_qb[seg], v);
                if (k != L - 1) atomicAdd(&s_nm[seg], 1u);
            }
        }
    }
    mpi = blockMaxU(mpi, &s_red);
    const double mp = mpi ? (double)mpi : EPS_S;
    __syncthreads();

    // per-segment: q = qb/nm (127 divides total), nnzq = sum nm, mq = max q
    double qseg = 0.0;
    unsigned int nmj = 0u;
    if (threadIdx.x < KQ) {
        nmj = s_nm[threadIdx.x];
        if (nmj > 0) qseg = (double)s_qb[threadIdx.x] / (double)nmj;
        s_q[threadIdx.x] = qseg;
    }
    unsigned int nnzq = (unsigned int)blockSumU64((unsigned long long)nmj, &s_red);
    double mq = blockMaxD((threadIdx.x < KQ && nmj > 0) ? qseg : -1e300, &s_red);
    mq = fmax(mq, EPS_S);   // zero-q bins (>=1 always: k=L-1) carry EPS logits

    // sq: per-segment grouped logsumexp + zero-q bins (count = L - nnzq)
    double sq = 0.0;
    if (threadIdx.x < KQ && nmj > 0) {
        double dq = qseg - mq;
        if (dq > EXP_CUT) sq = (double)nmj * exp(dq);
    }
    if (threadIdx.x == 0) {
        double dz = EPS_S - mq;
        if (dz > EXP_CUT) sq += (double)(L - (int)nnzq) * exp(dz);
    }
    // sp: per-bin, gated (only bins within 700 of the max can contribute)
    double sp = 0.0;
    {
        double gate = mp + EXP_CUT;
        #pragma unroll
        for (int t = 0; t < 4; t++) {
            int k = threadIdx.x + t * 256;
            if (k < L) {
                double pl = pv[t] ? (double)pv[t] : EPS_S;
                if (pl > gate) sp += exp(pl - mp);
            }
        }
    }
    sq = blockSumD(sq, &s_red);
    sp = blockSumD(sp, &s_red);
    const double lZp = mp + log(sp);
    const double lZq = mq + log(sq);

    // main sum: full per-bin KL term (this IS the complete KL; no extra shift)
    double kl = 0.0;
    {
        double gate = lZp + EXP_CUT;
        #pragma unroll
        for (int t = 0; t < 4; t++) {
            int k = threadIdx.x + t * 256;
            if (k < L) {
                double pl = pv[t] ? (double)pv[t] : EPS_S;
                if (pl > gate) {
                    int seg = min(k / m, KQ - 1);
                    bool assigned = (vv[t] != 0u) && (k != L - 1) && (s_nm[seg] > 0u);
                    double ql = assigned ? s_q[seg] : EPS_S;
                    double lp = pl - lZp;
                    double lq = ql - lZq;
                    kl += exp(lp) * (lp - lq);
                }
            }
        }
    }
    kl = blockSumD(kl, &s_red);
    if (threadIdx.x == 0)
        g_kl[blockIdx.x] = (nnzq > 0u) ? kl : (double)INFINITY;
}

// ---------------- argmin + threshold ----------------
__global__ void argmin_kernel(float* __restrict__ out) {
    __shared__ double sv[256];
    __shared__ int si[256];
    double best = (double)INFINITY;
    int bi = 0x7fffffff;
    for (int k = threadIdx.x; k < NCAND; k += blockDim.x) {
        double v = g_kl[k];
        if (v < best || (v == best && k < bi)) { best = v; bi = k; }
    }
    sv[threadIdx.x] = best; si[threadIdx.x] = bi;
    __syncthreads();
    for (int s = 128; s > 0; s >>= 1) {
        if (threadIdx.x < s) {
            double vo = sv[threadIdx.x + s];
            int io = si[threadIdx.x + s];
            if (vo < sv[threadIdx.x] || (vo == sv[threadIdx.x] && io < si[threadIdx.x])) {
                sv[threadIdx.x] = vo; si[threadIdx.x] = io;
            }
        }
        __syncthreads();
    }
    if (threadIdx.x == 0) {
        int i = IMIN + si[0];
        float a = __uint_as_float(g_absmax_bits);
        double thr = -(double)a + 2.0 * (double)a * (double)(i + HALFB + 1) / (double)NBINS;
        out[0] = (float)thr;
    }
}

extern "C" void kernel_launch(void* const* d_in, const int* in_sizes, int n_in,
                              void* d_out, int out_size) {
    const float* x = (const float*)d_in[0];
    int n = in_sizes[0];
    init_kernel<<<1, 1024>>>();
    absmax_kernel<<<1480, 256>>>(x, n);
    hist_kernel<<<1184, 256>>>(x, n);
    kl_kernel<<<NCAND, 256>>>();
    argmin_kernel<<<1, 256>>>((float*)d_out);
}

// round 7
// speedup vs baseline: 4.1419x; 1.0115x over previous
#include <cuda_runtime.h>
#include <math.h>

#define NBINS 1001
#define KQ 127
#define HALFB 500
#define EPS_S 1e-4
#define IMIN 63
#define NCAND 438
#define HIST_SUB 4
#define EXP_CUT -700.0

__device__ unsigned int g_absmax_bits;
__device__ unsigned int g_hist[NBINS];
__device__ unsigned int g_csum[NBINS + 1];
__device__ unsigned int g_total;
__device__ double g_kl[NCAND];

// ---------------- init ----------------
__global__ void init_kernel() {
    int t = threadIdx.x;
    if (t == 0) g_absmax_bits = 0u;
    for (int k = t; k < NBINS; k += blockDim.x) g_hist[k] = 0u;
}

// ---------------- absmax (forward sweep) ----------------
__global__ void absmax_kernel(const float* __restrict__ x, int n) {
    int n4 = n >> 2;
    const float4* x4 = (const float4*)x;
    float m = 0.f;
    int stride = gridDim.x * blockDim.x;
    for (int idx = blockIdx.x * blockDim.x + threadIdx.x; idx < n4; idx += stride) {
        float4 v = x4[idx];
        m = fmaxf(m, fmaxf(fmaxf(fabsf(v.x), fabsf(v.y)), fmaxf(fabsf(v.z), fabsf(v.w))));
    }
    if (blockIdx.x == 0 && threadIdx.x < (n & 3))
        m = fmaxf(m, fabsf(x[n4 * 4 + threadIdx.x]));
    #pragma unroll
    for (int o = 16; o; o >>= 1) m = fmaxf(m, __shfl_xor_sync(0xffffffffu, m, o));
    __shared__ float sm[8];
    int lane = threadIdx.x & 31, w = threadIdx.x >> 5;
    if (lane == 0) sm[w] = m;
    __syncthreads();
    if (w == 0) {
        m = (lane < 8) ? sm[lane] : 0.f;
        #pragma unroll
        for (int o = 4; o; o >>= 1) m = fmaxf(m, __shfl_xor_sync(0xffffffffu, m, o));
        if (lane == 0) atomicMax(&g_absmax_bits, __float_as_uint(m));
    }
}

// ---------------- histogram (REVERSE sweep for L2 reuse) ----------------
__device__ __forceinline__ int bin_of(float c, float a, float inv, float step) {
    int b = (int)(__fmul_rn(__fadd_rn(c, a), inv));
    #pragma unroll
    for (int it = 0; it < 3; it++) {
        float e0 = __fadd_rn(__fmul_rn((float)b, step), -a);
        if (c < e0) { b -= 1; continue; }
        float e1 = __fadd_rn(__fmul_rn((float)(b + 1), step), -a);
        if (c >= e1) { b += 1; continue; }
        break;
    }
    return max(0, min(NBINS - 1, b));
}

__global__ void hist_kernel(const float* __restrict__ x, int n) {
    __shared__ unsigned int sh[HIST_SUB][NBINS];
    unsigned int* shf = &sh[0][0];
    for (int k = threadIdx.x; k < HIST_SUB * NBINS; k += blockDim.x) shf[k] = 0u;
    __syncthreads();

    float a = __uint_as_float(g_absmax_bits);
    float step = __fdiv_rn(__fmul_rn(2.0f, a), (float)NBINS);
    float inv = __fdiv_rn((float)NBINS, __fmul_rn(2.0f, a));
    unsigned int* hsub = sh[(threadIdx.x >> 5) & (HIST_SUB - 1)];

    int n4 = n >> 2;
    const float4* x4 = (const float4*)x;
    int stride = gridDim.x * blockDim.x;
    // reverse sweep: absmax ended with high addresses resident in L2
    for (int idx = blockIdx.x * blockDim.x + threadIdx.x; idx < n4; idx += stride) {
        float4 v = x4[n4 - 1 - idx];
        atomicAdd(&hsub[bin_of(v.x, a, inv, step)], 1u);
        atomicAdd(&hsub[bin_of(v.y, a, inv, step)], 1u);
        atomicAdd(&hsub[bin_of(v.z, a, inv, step)], 1u);
        atomicAdd(&hsub[bin_of(v.w, a, inv, step)], 1u);
    }
    if (blockIdx.x == 0 && threadIdx.x < (n & 3)) {
        float c = x[n4 * 4 + threadIdx.x];
        atomicAdd(&hsub[bin_of(c, a, inv, step)], 1u);
    }
    __syncthreads();
    for (int k = threadIdx.x; k < NBINS; k += blockDim.x) {
        unsigned int s = 0;
        #pragma unroll
        for (int j = 0; j < HIST_SUB; j++) s += sh[j][k];
        if (s) atomicAdd(&g_hist[k], s);
    }
}

// ---------------- prep: exclusive prefix sum of histogram ----------------
__global__ void prep_kernel() {  // 1024 threads, one block
    __shared__ unsigned int wsum[32];
    int tid = threadIdx.x;
    unsigned int v = (tid < NBINS) ? g_hist[tid] : 0u;
    unsigned int inc = v;
    #pragma unroll
    for (int o = 1; o < 32; o <<= 1) {
        unsigned int t = __shfl_up_sync(0xffffffffu, inc, o);
        if ((tid & 31) >= o) inc += t;
    }
    if ((tid & 31) == 31) wsum[tid >> 5] = inc;
    __syncthreads();
    if (tid < 32) {
        unsigned int s = wsum[tid];
        #pragma unroll
        for (int o = 1; o < 32; o <<= 1) {
            unsigned int t = __shfl_up_sync(0xffffffffu, s, o);
            if (tid >= o) s += t;
        }
        wsum[tid] = s;
    }
    __syncthreads();
    unsigned int offset = (tid >= 32) ? wsum[(tid >> 5) - 1] : 0u;
    unsigned int incl = inc + offset;
    if (tid < NBINS) g_csum[tid] = incl - v;      // exclusive prefix
    if (tid == NBINS - 1) { g_csum[NBINS] = incl; g_total = incl; }
}

// ---------------- reductions ----------------
template <typename T>
__device__ __forceinline__ T warpSumT(T v) {
    #pragma unroll
    for (int o = 16; o; o >>= 1) v += __shfl_xor_sync(0xffffffffu, v, o);
    return v;
}
__device__ __forceinline__ unsigned int warpMaxU(unsigned int v) {
    #pragma unroll
    for (int o = 16; o; o >>= 1) v = max(v, __shfl_xor_sync(0xffffffffu, v, o));
    return v;
}
__device__ __forceinline__ double warpMaxD(double v) {
    #pragma unroll
    for (int o = 16; o; o >>= 1) v = fmax(v, __shfl_xor_sync(0xffffffffu, v, o));
    return v;
}

struct RedShared {
    double d[16];
    unsigned long long u[8];
};

__device__ __forceinline__ double blockSumD(double v, RedShared* sh) {
    int lane = threadIdx.x & 31, w = threadIdx.x >> 5;
    v = warpSumT(v);
    if (lane == 0) sh->d[w] = v;
    __syncthreads();
    if (w == 0) {
        double t = (lane < 8) ? sh->d[lane] : 0.0;
        t = warpSumT(t);
        if (lane == 0) sh->d[0] = t;
    }
    __syncthreads();
    double r = sh->d[0];
    __syncthreads();
    return r;
}
// fused: two double sums in one barrier round
__device__ __forceinline__ void blockSum2(double& a, double& b, RedShared* sh) {
    int lane = threadIdx.x & 31, w = threadIdx.x >> 5;
    a = warpSumT(a); b = warpSumT(b);
    if (lane == 0) { sh->d[w] = a; sh->d[8 + w] = b; }
    __syncthreads();
    if (w == 0) {
        double ta = (lane < 8) ? sh->d[lane] : 0.0;
        double tb = (lane < 8) ? sh->d[8 + lane] : 0.0;
        ta = warpSumT(ta); tb = warpSumT(tb);
        if (lane == 0) { sh->d[0] = ta; sh->d[8] = tb; }
    }
    __syncthreads();
    a = sh->d[0]; b = sh->d[8];
    __syncthreads();
}
// fused: unsigned sum + double max in one barrier round
__device__ __forceinline__ void blockSumU_MaxD(unsigned int& s, double& mx, RedShared* sh) {
    int lane = threadIdx.x & 31, w = threadIdx.x >> 5;
    s = warpSumT(s); mx = warpMaxD(mx);
    if (lane == 0) { sh->u[w] = s; sh->d[w] = mx; }
    __syncthreads();
    if (w == 0) {
        unsigned int ts = (lane < 8) ? (unsigned int)sh->u[lane] : 0u;
        double tm = (lane < 8) ? sh->d[lane] : -1e300;
        ts = warpSumT(ts); tm = warpMaxD(tm);
        if (lane == 0) { sh->u[0] = ts; sh->d[0] = tm; }
    }
    __syncthreads();
    s = (unsigned int)sh->u[0]; mx = sh->d[0];
    __syncthreads();
}
__device__ __forceinline__ unsigned int blockMaxU(unsigned int v, RedShared* sh) {
    int lane = threadIdx.x & 31, w = threadIdx.x >> 5;
    v = warpMaxU(v);
    if (lane == 0) sh->u[w] = v;
    __syncthreads();
    if (w == 0) {
        unsigned int t = (lane < 8) ? (unsigned int)sh->u[lane] : 0u;
        t = warpMaxU(t);
        if (lane == 0) sh->u[0] = t;
    }
    __syncthreads();
    unsigned int r = (unsigned int)sh->u[0];
    __syncthreads();
    return r;
}

// ---------------- per-candidate KL ----------------
// KL = sum_k exp(lp_k)*(lp_k - lq_k); q has <=127 distinct values (one/segment);
// segments are contiguous k-ranges -> serial per-thread sums, no atomics;
// bins with exp(lp) < e^-700 contribute < 1e-301 and are skipped exactly.
__global__ void kl_kernel() {
    const int i = IMIN + (int)blockIdx.x;
    const int L = 2 * i + 1;
    const int start = HALFB - i;
    const int stop = HALFB + i + 1;
    const int m = L / KQ;

    __shared__ unsigned int s_h[NBINS];
    __shared__ double s_q[KQ];
    __shared__ unsigned int s_nm[KQ];
    __shared__ RedShared s_red;

    for (int k = threadIdx.x; k < NBINS; k += 256) s_h[k] = g_hist[k];
    __syncthreads();

    const unsigned int left = g_csum[start];
    const unsigned int right = g_total - g_csum[stop];

    // per-bin p values + block max p
    unsigned int pv[4], vv[4];
    unsigned int mpi = 0u;
    #pragma unroll
    for (int t = 0; t < 4; t++) {
        int k = threadIdx.x + t * 256;
        pv[t] = 0u; vv[t] = 0u;
        if (k < L) {
            unsigned int v = s_h[start + k];
            vv[t] = v;
            unsigned int p = v;
            if (k == 0) p += left;
            if (k == L - 1) p += right;
            pv[t] = p;
            mpi = max(mpi, p);
        }
    }
    mpi = blockMaxU(mpi, &s_red);
    const double mp = mpi ? (double)mpi : EPS_S;

    // per-segment sums/counts: thread j owns contiguous range (no atomics)
    double qseg = 0.0;
    unsigned int nmj = 0u;
    if (threadIdx.x < KQ) {
        int j = threadIdx.x;
        int k0 = j * m;
        int k1 = (j == KQ - 1) ? L : (k0 + m);
        unsigned int sum = 0u, cnt = 0u;
        for (int k = k0; k < k1; k++) {
            unsigned int v = s_h[start + k];
            sum += v;
            cnt += (v != 0u && k != L - 1) ? 1u : 0u;
        }
        nmj = cnt;
        if (cnt > 0u) qseg = (double)sum / (double)cnt;
        s_q[j] = qseg;
        s_nm[j] = cnt;
    }
    // fused: nnzq (sum) + mq (max) — also serves as the barrier making s_q/s_nm visible
    unsigned int nnzq = nmj;
    double mq = (threadIdx.x < KQ && nmj > 0u) ? qseg : -1e300;
    blockSumU_MaxD(nnzq, mq, &s_red);
    mq = fmax(mq, EPS_S);   // zero-q bins always exist (k=L-1)

    // sq: grouped per-segment; sp: per-bin gated
    double sq = 0.0;
    if (threadIdx.x < KQ && nmj > 0u) {
        double dq = qseg - mq;
        if (dq > EXP_CUT) sq = (double)nmj * exp(dq);
    }
    if (threadIdx.x == 0) {
        double dz = EPS_S - mq;
        if (dz > EXP_CUT) sq += (double)(L - (int)nnzq) * exp(dz);
    }
    double sp = 0.0;
    {
        double gate = mp + EXP_CUT;
        #pragma unroll
        for (int t = 0; t < 4; t++) {
            int k = threadIdx.x + t * 256;
            if (k < L) {
                double pl = pv[t] ? (double)pv[t] : EPS_S;
                if (pl > gate) sp += exp(pl - mp);
            }
        }
    }
    blockSum2(sp, sq, &s_red);
    const double lZp = mp + log(sp);
    const double lZq = mq + log(sq);

    // main sum: complete per-bin KL (gated; skipped terms < 1e-301)
    double kl = 0.0;
    {
        double gate = lZp + EXP_CUT;
        #pragma unroll
        for (int t = 0; t < 4; t++) {
            int k = threadIdx.x + t * 256;
            if (k < L) {
                double pl = pv[t] ? (double)pv[t] : EPS_S;
                if (pl > gate) {
                    int seg = min(k / m, KQ - 1);
                    bool assigned = (vv[t] != 0u) && (k != L - 1) && (s_nm[seg] > 0u);
                    double ql = assigned ? s_q[seg] : EPS_S;
                    double lp = pl - lZp;
                    double lq = ql - lZq;
                    kl += exp(lp) * (lp - lq);
                }
            }
        }
    }
    kl = blockSumD(kl, &s_red);
    if (threadIdx.x == 0)
        g_kl[blockIdx.x] = (nnzq > 0u) ? kl : (double)INFINITY;
}

// ---------------- argmin + threshold ----------------
__global__ void argmin_kernel(float* __restrict__ out) {
    __shared__ double sv[256];
    __shared__ int si[256];
    double best = (double)INFINITY;
    int bi = 0x7fffffff;
    for (int k = threadIdx.x; k < NCAND; k += blockDim.x) {
        double v = g_kl[k];
        if (v < best || (v == best && k < bi)) { best = v; bi = k; }
    }
    sv[threadIdx.x] = best; si[threadIdx.x] = bi;
    __syncthreads();
    for (int s = 128; s > 0; s >>= 1) {
        if (threadIdx.x < s) {
            double vo = sv[threadIdx.x + s];
            int io = si[threadIdx.x + s];
            if (vo < sv[threadIdx.x] || (vo == sv[threadIdx.x] && io < si[threadIdx.x])) {
                sv[threadIdx.x] = vo; si[threadIdx.x] = io;
            }
        }
        __syncthreads();
    }
    if (threadIdx.x == 0) {
        int i = IMIN + si[0];
        float a = __uint_as_float(g_absmax_bits);
        double thr = -(double)a + 2.0 * (double)a * (double)(i + HALFB + 1) / (double)NBINS;
        out[0] = (float)thr;
    }
}

extern "C" void kernel_launch(void* const* d_in, const int* in_sizes, int n_in,
                              void* d_out, int out_size) {
    const float* x = (const float*)d_in[0];
    int n = in_sizes[0];
    init_kernel<<<1, 1024>>>();
    absmax_kernel<<<1480, 256>>>(x, n);
    hist_kernel<<<1184, 256>>>(x, n);
    prep_kernel<<<1, 1024>>>();
    kl_kernel<<<NCAND, 256>>>();
    argmin_kernel<<<1, 256>>>((float*)d_out);
}

// round 9
// speedup vs baseline: 4.6426x; 1.1209x over previous
#include <cuda_runtime.h>
#include <math.h>

#define NBINS 1001
#define KQ 127
#define HALFB 500
#define EPS_S 1e-4
#define IMIN 63
#define NCAND 438
#define HIST_SUB 4
#define EXP_CUT -700.0
#define HIST_GRID 1184
#define BAND 2e-3f

__device__ unsigned int g_absmax_bits;   // zero at load; argmin re-zeroes each call
__device__ unsigned int g_hist[NBINS];   // zero at load; argmin re-zeroes each call
__device__ unsigned int g_csum[NBINS + 1];
__device__ unsigned int g_total;
__device__ unsigned int g_done;          // hist completion ticket; self-resetting
__device__ double g_kl[NCAND];

// ---------------- absmax ----------------
__global__ void absmax_kernel(const float* __restrict__ x, int n) {
    int n4 = n >> 2;
    const float4* x4 = (const float4*)x;
    float m = 0.f;
    int stride = gridDim.x * blockDim.x;
    for (int idx = blockIdx.x * blockDim.x + threadIdx.x; idx < n4; idx += stride) {
        float4 v = x4[idx];
        m = fmaxf(m, fmaxf(fmaxf(fabsf(v.x), fabsf(v.y)), fmaxf(fabsf(v.z), fabsf(v.w))));
    }
    if (blockIdx.x == 0 && threadIdx.x < (n & 3))
        m = fmaxf(m, fabsf(x[n4 * 4 + threadIdx.x]));
    #pragma unroll
    for (int o = 16; o; o >>= 1) m = fmaxf(m, __shfl_xor_sync(0xffffffffu, m, o));
    __shared__ float sm[8];
    int lane = threadIdx.x & 31, w = threadIdx.x >> 5;
    if (lane == 0) sm[w] = m;
    __syncthreads();
    if (w == 0) {
        m = (lane < 8) ? sm[lane] : 0.f;
        #pragma unroll
        for (int o = 4; o; o >>= 1) m = fmaxf(m, __shfl_xor_sync(0xffffffffu, m, o));
        if (lane == 0) atomicMax(&g_absmax_bits, __float_as_uint(m));
    }
}

// ---------------- binning ----------------
// Fast path: fp32 estimate floor((c+a)*inv). Estimate error + fp32-edge deviation
// is < 3.5e-4 bins, so the floor is provably correct unless the fractional part
// lies within BAND of a boundary; only then verify against the exact fp32 edges
// (linspace semantics: edge_k = fl(fl(k*step) - a), searchsorted-right - 1).
__device__ __forceinline__ int bin_of(float c, float a, float inv, float step) {
    float y = __fmul_rn(__fadd_rn(c, a), inv);          // >= 0
    int b = (int)y;
    float fr = y - (float)b;
    if (fr < BAND || fr > 1.0f - BAND) {
        float e0 = __fadd_rn(__fmul_rn((float)b, step), -a);
        float e1 = __fadd_rn(__fmul_rn((float)(b + 1), step), -a);
        b += (c >= e1) ? 1 : 0;
        b -= (c < e0) ? 1 : 0;
    }
    return max(0, min(NBINS - 1, b));
}

// ---------------- histogram + fused prefix-scan (last block) ----------------
__global__ void hist_kernel(const float* __restrict__ x, int n) {
    __shared__ unsigned int sh[HIST_SUB][NBINS];
    unsigned int* shf = &sh[0][0];
    for (int k = threadIdx.x; k < HIST_SUB * NBINS; k += blockDim.x) shf[k] = 0u;
    __syncthreads();

    float a = __uint_as_float(g_absmax_bits);
    float step = __fdiv_rn(__fmul_rn(2.0f, a), (float)NBINS);
    float inv = __fdiv_rn((float)NBINS, __fmul_rn(2.0f, a));
    unsigned int* hsub = sh[(threadIdx.x >> 5) & (HIST_SUB - 1)];

    int n4 = n >> 2;
    int half = n4 >> 1;
    const float4* x4 = (const float4*)x;
    int stride = gridDim.x * blockDim.x;
    for (int idx = blockIdx.x * blockDim.x + threadIdx.x; idx < half; idx += stride) {
        float4 u = x4[idx];
        float4 v = x4[idx + half];
        atomicAdd(&hsub[bin_of(u.x, a, inv, step)], 1u);
        atomicAdd(&hsub[bin_of(u.y, a, inv, step)], 1u);
        atomicAdd(&hsub[bin_of(u.z, a, inv, step)], 1u);
        atomicAdd(&hsub[bin_of(u.w, a, inv, step)], 1u);
        atomicAdd(&hsub[bin_of(v.x, a, inv, step)], 1u);
        atomicAdd(&hsub[bin_of(v.y, a, inv, step)], 1u);
        atomicAdd(&hsub[bin_of(v.z, a, inv, step)], 1u);
        atomicAdd(&hsub[bin_of(v.w, a, inv, step)], 1u);
    }
    // leftovers beyond 2*half float4s
    int done = half * 8;
    if (blockIdx.x == 0 && threadIdx.x < (n - done)) {
        float c = x[done + threadIdx.x];
        atomicAdd(&hsub[bin_of(c, a, inv, step)], 1u);
    }
    __syncthreads();
    for (int k = threadIdx.x; k < NBINS; k += blockDim.x) {
        unsigned int s = 0;
        #pragma unroll
        for (int j = 0; j < HIST_SUB; j++) s += sh[j][k];
        if (s) atomicAdd(&g_hist[k], s);
    }

    // ---- fused prep: last block to finish performs the exclusive scan ----
    __shared__ unsigned int s_last;
    __threadfence();
    if (threadIdx.x == 0)
        s_last = (atomicAdd(&g_done, 1u) == (unsigned int)(gridDim.x - 1)) ? 1u : 0u;
    __syncthreads();
    if (s_last) {
        __threadfence();  // acquire: make all blocks' g_hist atomics visible
        __shared__ unsigned int tsum[256];
        __shared__ unsigned int wex[9];
        int t = threadIdx.x;
        // blocked load: thread t owns bins [4t, 4t+4)
        unsigned int hv[4], loc[4];
        unsigned int s = 0;
        #pragma unroll
        for (int j = 0; j < 4; j++) {
            int k = 4 * t + j;
            hv[j] = (k < NBINS) ? g_hist[k] : 0u;
            loc[j] = s;
            s += hv[j];
        }
        tsum[t] = s;
        __syncthreads();
        // scan 256 thread-sums: warp inclusive scans + serial warp-total scan
        unsigned int v = tsum[t];
        unsigned int inc = v;
        int lane = t & 31, w = t >> 5;
        #pragma unroll
        for (int o = 1; o < 32; o <<= 1) {
            unsigned int q = __shfl_up_sync(0xffffffffu, inc, o);
            if (lane >= o) inc += q;
        }
        if (lane == 31) wex[w + 1] = inc;
        __syncthreads();
        if (t == 0) {
            wex[0] = 0u;
            for (int j = 1; j < 8; j++) wex[j + 1] += wex[j];
        }
        __syncthreads();
        unsigned int base = wex[w] + inc - v;   // exclusive prefix of thread t
        #pragma unroll
        for (int j = 0; j < 4; j++) {
            int k = 4 * t + j;
            if (k < NBINS) g_csum[k] = base + loc[j];
        }
        if (t == 255) {
            unsigned int tot = base + loc[3] + hv[3];
            g_csum[NBINS] = tot;
            g_total = tot;
            g_done = 0u;   // reset ticket for the next call
        }
    }
}

// ---------------- reductions ----------------
template <typename T>
__device__ __forceinline__ T warpSumT(T v) {
    #pragma unroll
    for (int o = 16; o; o >>= 1) v += __shfl_xor_sync(0xffffffffu, v, o);
    return v;
}
__device__ __forceinline__ unsigned int warpMaxU(unsigned int v) {
    #pragma unroll
    for (int o = 16; o; o >>= 1) v = max(v, __shfl_xor_sync(0xffffffffu, v, o));
    return v;
}
__device__ __forceinline__ double warpMaxD(double v) {
    #pragma unroll
    for (int o = 16; o; o >>= 1) v = fmax(v, __shfl_xor_sync(0xffffffffu, v, o));
    return v;
}

struct RedShared {
    double d[16];
    unsigned long long u[8];
};

__device__ __forceinline__ double blockSumD(double v, RedShared* sh) {
    int lane = threadIdx.x & 31, w = threadIdx.x >> 5;
    v = warpSumT(v);
    if (lane == 0) sh->d[w] = v;
    __syncthreads();
    if (w == 0) {
        double t = (lane < 8) ? sh->d[lane] : 0.0;
        t = warpSumT(t);
        if (lane == 0) sh->d[0] = t;
    }
    __syncthreads();
    double r = sh->d[0];
    __syncthreads();
    return r;
}
__device__ __forceinline__ void blockSum2(double& a, double& b, RedShared* sh) {
    int lane = threadIdx.x & 31, w = threadIdx.x >> 5;
    a = warpSumT(a); b = warpSumT(b);
    if (lane == 0) { sh->d[w] = a; sh->d[8 + w] = b; }
    __syncthreads();
    if (w == 0) {
        double ta = (lane < 8) ? sh->d[lane] : 0.0;
        double tb = (lane < 8) ? sh->d[8 + lane] : 0.0;
        ta = warpSumT(ta); tb = warpSumT(tb);
        if (lane == 0) { sh->d[0] = ta; sh->d[8] = tb; }
    }
    __syncthreads();
    a = sh->d[0]; b = sh->d[8];
    __syncthreads();
}
__device__ __forceinline__ void blockSumU_MaxD(unsigned int& s, double& mx, RedShared* sh) {
    int lane = threadIdx.x & 31, w = threadIdx.x >> 5;
    s = warpSumT(s); mx = warpMaxD(mx);
    if (lane == 0) { sh->u[w] = s; sh->d[w] = mx; }
    __syncthreads();
    if (w == 0) {
        unsigned int ts = (lane < 8) ? (unsigned int)sh->u[lane] : 0u;
        double tm = (lane < 8) ? sh->d[lane] : -1e300;
        ts = warpSumT(ts); tm = warpMaxD(tm);
        if (lane == 0) { sh->u[0] = ts; sh->d[0] = tm; }
    }
    __syncthreads();
    s = (unsigned int)sh->u[0]; mx = sh->d[0];
    __syncthreads();
}
__device__ __forceinline__ unsigned int blockMaxU(unsigned int v, RedShared* sh) {
    int lane = threadIdx.x & 31, w = threadIdx.x >> 5;
    v = warpMaxU(v);
    if (lane == 0) sh->u[w] = v;
    __syncthreads();
    if (w == 0) {
        unsigned int t = (lane < 8) ? (unsigned int)sh->u[lane] : 0u;
        t = warpMaxU(t);
        if (lane == 0) sh->u[0] = t;
    }
    __syncthreads();
    unsigned int r = (unsigned int)sh->u[0];
    __syncthreads();
    return r;
}

// ---------------- per-candidate KL ----------------
__global__ void kl_kernel() {
    const int i = IMIN + (int)blockIdx.x;
    const int L = 2 * i + 1;
    const int start = HALFB - i;
    const int stop = HALFB + i + 1;
    const int m = L / KQ;

    __shared__ unsigned int s_h[NBINS];
    __shared__ double s_q[KQ];
    __shared__ unsigned int s_nm[KQ];
    __shared__ RedShared s_red;

    for (int k = threadIdx.x; k < NBINS; k += 256) s_h[k] = g_hist[k];
    __syncthreads();

    const unsigned int left = g_csum[start];
    const unsigned int right = g_total - g_csum[stop];

    unsigned int pv[4], vv[4];
    unsigned int mpi = 0u;
    #pragma unroll
    for (int t = 0; t < 4; t++) {
        int k = threadIdx.x + t * 256;
        pv[t] = 0u; vv[t] = 0u;
        if (k < L) {
            unsigned int v = s_h[start + k];
            vv[t] = v;
            unsigned int p = v;
            if (k == 0) p += left;
            if (k == L - 1) p += right;
            pv[t] = p;
            mpi = max(mpi, p);
        }
    }
    mpi = blockMaxU(mpi, &s_red);
    const double mp = mpi ? (double)mpi : EPS_S;

    double qseg = 0.0;
    unsigned int nmj = 0u;
    if (threadIdx.x < KQ) {
        int j = threadIdx.x;
        int k0 = j * m;
        int k1 = (j == KQ - 1) ? L : (k0 + m);
        unsigned int sum = 0u, cnt = 0u;
        for (int k = k0; k < k1; k++) {
            unsigned int v = s_h[start + k];
            sum += v;
            cnt += (v != 0u && k != L - 1) ? 1u : 0u;
        }
        nmj = cnt;
        if (cnt > 0u) qseg = (double)sum / (double)cnt;
        s_q[j] = qseg;
        s_nm[j] = cnt;
    }
    unsigned int nnzq = nmj;
    double mq = (threadIdx.x < KQ && nmj > 0u) ? qseg : -1e300;
    blockSumU_MaxD(nnzq, mq, &s_red);
    mq = fmax(mq, EPS_S);

    double sq = 0.0;
    if (threadIdx.x < KQ && nmj > 0u) {
        double dq = qseg - mq;
        if (dq > EXP_CUT) sq = (double)nmj * exp(dq);
    }
    if (threadIdx.x == 0) {
        double dz = EPS_S - mq;
        if (dz > EXP_CUT) sq += (double)(L - (int)nnzq) * exp(dz);
    }
    double sp = 0.0;
    {
        double gate = mp + EXP_CUT;
        #pragma unroll
        for (int t = 0; t < 4; t++) {
            int k = threadIdx.x + t * 256;
            if (k < L) {
                double pl = pv[t] ? (double)pv[t] : EPS_S;
                if (pl > gate) sp += exp(pl - mp);
            }
        }
    }
    blockSum2(sp, sq, &s_red);
    const double lZp = mp + log(sp);
    const double lZq = mq + log(sq);

    double kl = 0.0;
    {
        double gate = lZp + EXP_CUT;
        #pragma unroll
        for (int t = 0; t < 4; t++) {
            int k = threadIdx.x + t * 256;
            if (k < L) {
                double pl = pv[t] ? (double)pv[t] : EPS_S;
                if (pl > gate) {
                    int seg = min(k / m, KQ - 1);
                    bool assigned = (vv[t] != 0u) && (k != L - 1) && (s_nm[seg] > 0u);
                    double ql = assigned ? s_q[seg] : EPS_S;
                    double lp = pl - lZp;
                    double lq = ql - lZq;
                    kl += exp(lp) * (lp - lq);
                }
            }
        }
    }
    kl = blockSumD(kl, &s_red);
    if (threadIdx.x == 0)
        g_kl[blockIdx.x] = (nnzq > 0u) ? kl : (double)INFINITY;
}

// ---------------- argmin + threshold + state reset ----------------
__global__ void argmin_kernel(float* __restrict__ out) {
    __shared__ double sv[256];
    __shared__ int si[256];
    double best = (double)INFINITY;
    int bi = 0x7fffffff;
    for (int k = threadIdx.x; k < NCAND; k += blockDim.x) {
        double v = g_kl[k];
        if (v < best || (v == best && k < bi)) { best = v; bi = k; }
    }
    sv[threadIdx.x] = best; si[threadIdx.x] = bi;
    __syncthreads();
    for (int s = 128; s > 0; s >>= 1) {
        if (threadIdx.x < s) {
            double vo = sv[threadIdx.x + s];
            int io = si[threadIdx.x + s];
            if (vo < sv[threadIdx.x] || (vo == sv[threadIdx.x] && io < si[threadIdx.x])) {
                sv[threadIdx.x] = vo; si[threadIdx.x] = io;
            }
        }
        __syncthreads();
    }
    if (threadIdx.x == 0) {
        int i = IMIN + si[0];
        float a = __uint_as_float(g_absmax_bits);
        double thr = -(double)a + 2.0 * (double)a * (double)(i + HALFB + 1) / (double)NBINS;
        out[0] = (float)thr;
    }
    // restore the zero-state invariant for the next call (replaces init_kernel)
    for (int k = threadIdx.x; k < NBINS; k += blockDim.x) g_hist[k] = 0u;
    if (threadIdx.x == 0) g_absmax_bits = 0u;
}

extern "C" void kernel_launch(void* const* d_in, const int* in_sizes, int n_in,
                              void* d_out, int out_size) {
    const float* x = (const float*)d_in[0];
    int n = in_sizes[0];
    absmax_kernel<<<1480, 256>>>(x, n);
    hist_kernel<<<HIST_GRID, 256>>>(x, n);
    kl_kernel<<<NCAND, 256>>>();
    argmin_kernel<<<1, 256>>>((float*)d_out);
}

// round 10
// speedup vs baseline: 4.9552x; 1.0673x over previous
#include <cuda_runtime.h>
#include <math.h>

#define NBINS 1001
#define KQ 127
#define HALFB 500
#define EPS_S 1e-4
#define IMIN 63
#define NCAND 438
#define HIST_SUB 4
#define EXP_CUT -700.0
#define BAND 2e-3f
#define MAIN_GRID 592   // 4 blocks/SM x 148 SMs; __launch_bounds__(256,4) guarantees residency

__device__ unsigned int g_absmax_bits;   // zero at load; final kl block re-zeroes
__device__ unsigned int g_hist[NBINS];   // zero at load; final kl block re-zeroes
__device__ unsigned int g_csum[NBINS + 1];
__device__ unsigned int g_total;
__device__ unsigned int g_bar;           // grid barrier arrive counter (reset by kl final block)
__device__ unsigned int g_done;          // hist scan ticket (reset by kl final block)
__device__ unsigned int g_done2;         // kl argmin ticket (reset by kl final block)
__device__ double g_kl[NCAND];

// ---------------- binning ----------------
// Fast path: fp32 estimate floor((c+a)*inv); provably correct unless the
// fractional part is within BAND of a boundary (estimate+edge error < 3.5e-4
// bins), in which case verify against exact fp32 linspace edges.
__device__ __forceinline__ int bin_of(float c, float a, float inv, float step) {
    float y = __fmul_rn(__fadd_rn(c, a), inv);
    int b = (int)y;
    float fr = y - (float)b;
    if (fr < BAND || fr > 1.0f - BAND) {
        float e0 = __fadd_rn(__fmul_rn((float)b, step), -a);
        float e1 = __fadd_rn(__fmul_rn((float)(b + 1), step), -a);
        b += (c >= e1) ? 1 : 0;
        b -= (c < e0) ? 1 : 0;
    }
    return max(0, min(NBINS - 1, b));
}

// ---------------- fused absmax + grid barrier + histogram + scan ----------------
__global__ void __launch_bounds__(256, 4) main_kernel(const float* __restrict__ x, int n) {
    __shared__ unsigned int sh[HIST_SUB][NBINS];
    unsigned int* shf = &sh[0][0];
    for (int k = threadIdx.x; k < HIST_SUB * NBINS; k += 256) shf[k] = 0u;

    const int n4 = n >> 2;
    const float4* x4 = (const float4*)x;
    const int G = gridDim.x;
    const int b = blockIdx.x;
    const int lo = (int)((long long)b * n4 / G);
    const int hi = (int)((long long)(b + 1) * n4 / G);

    // ---- phase 1: absmax over own chunk (forward sweep) ----
    float m = 0.f;
    for (int idx = lo + threadIdx.x; idx < hi; idx += 256) {
        float4 v = x4[idx];
        m = fmaxf(m, fmaxf(fmaxf(fabsf(v.x), fabsf(v.y)), fmaxf(fabsf(v.z), fabsf(v.w))));
    }
    if (b == 0 && threadIdx.x < (n & 3))
        m = fmaxf(m, fabsf(x[n4 * 4 + threadIdx.x]));
    #pragma unroll
    for (int o = 16; o; o >>= 1) m = fmaxf(m, __shfl_xor_sync(0xffffffffu, m, o));
    __shared__ float sm[8];
    int lane = threadIdx.x & 31, w = threadIdx.x >> 5;
    if (lane == 0) sm[w] = m;
    __syncthreads();
    if (w == 0) {
        m = (lane < 8) ? sm[lane] : 0.f;
        #pragma unroll
        for (int o = 4; o; o >>= 1) m = fmaxf(m, __shfl_xor_sync(0xffffffffu, m, o));
        if (lane == 0) atomicMax(&g_absmax_bits, __float_as_uint(m));
    }

    // ---- grid barrier (all blocks resident by __launch_bounds__(256,4)) ----
    __threadfence();
    __syncthreads();
    if (threadIdx.x == 0) {
        atomicAdd(&g_bar, 1u);
        while (*(volatile unsigned int*)&g_bar < (unsigned int)G) { }
    }
    __syncthreads();

    const float a = __uint_as_float(*(volatile unsigned int*)&g_absmax_bits);
    const float step = __fdiv_rn(__fmul_rn(2.0f, a), (float)NBINS);
    const float inv = __fdiv_rn((float)NBINS, __fmul_rn(2.0f, a));
    unsigned int* hsub = sh[(threadIdx.x >> 5) & (HIST_SUB - 1)];

    // ---- phase 2: histogram over own chunk, REVERSE sweep (LIFO L2 reuse) ----
    for (int idx = hi - 1 - threadIdx.x; idx >= lo; idx -= 256) {
        float4 v = x4[idx];
        atomicAdd(&hsub[bin_of(v.x, a, inv, step)], 1u);
        atomicAdd(&hsub[bin_of(v.y, a, inv, step)], 1u);
        atomicAdd(&hsub[bin_of(v.z, a, inv, step)], 1u);
        atomicAdd(&hsub[bin_of(v.w, a, inv, step)], 1u);
    }
    if (b == 0 && threadIdx.x < (n & 3)) {
        float c = x[n4 * 4 + threadIdx.x];
        atomicAdd(&hsub[bin_of(c, a, inv, step)], 1u);
    }
    __syncthreads();
    for (int k = threadIdx.x; k < NBINS; k += 256) {
        unsigned int s = 0;
        #pragma unroll
        for (int j = 0; j < HIST_SUB; j++) s += sh[j][k];
        if (s) atomicAdd(&g_hist[k], s);
    }

    // ---- fused scan: last block to finish builds the exclusive prefix ----
    __shared__ unsigned int s_last;
    __threadfence();
    if (threadIdx.x == 0)
        s_last = (atomicAdd(&g_done, 1u) == (unsigned int)(G - 1)) ? 1u : 0u;
    __syncthreads();
    if (s_last) {
        __threadfence();
        __shared__ unsigned int tsum[256];
        __shared__ unsigned int wex[9];
        int t = threadIdx.x;
        unsigned int hv[4], loc[4];
        unsigned int s = 0;
        #pragma unroll
        for (int j = 0; j < 4; j++) {
            int k = 4 * t + j;
            hv[j] = (k < NBINS) ? *(volatile unsigned int*)&g_hist[k] : 0u;
            loc[j] = s;
            s += hv[j];
        }
        tsum[t] = s;
        __syncthreads();
        unsigned int v = tsum[t];
        unsigned int inc = v;
        #pragma unroll
        for (int o = 1; o < 32; o <<= 1) {
            unsigned int q = __shfl_up_sync(0xffffffffu, inc, o);
            if (lane >= o) inc += q;
        }
        if (lane == 31) wex[w + 1] = inc;
        __syncthreads();
        if (t == 0) {
            wex[0] = 0u;
            for (int j = 1; j < 8; j++) wex[j + 1] += wex[j];
        }
        __syncthreads();
        unsigned int base = wex[w] + inc - v;
        #pragma unroll
        for (int j = 0; j < 4; j++) {
            int k = 4 * t + j;
            if (k < NBINS) g_csum[k] = base + loc[j];
        }
        if (t == 255) {
            unsigned int tot = base + loc[3] + hv[3];
            g_csum[NBINS] = tot;
            g_total = tot;
        }
    }
}

// ---------------- reductions ----------------
template <typename T>
__device__ __forceinline__ T warpSumT(T v) {
    #pragma unroll
    for (int o = 16; o; o >>= 1) v += __shfl_xor_sync(0xffffffffu, v, o);
    return v;
}
__device__ __forceinline__ unsigned int warpMaxU(unsigned int v) {
    #pragma unroll
    for (int o = 16; o; o >>= 1) v = max(v, __shfl_xor_sync(0xffffffffu, v, o));
    return v;
}
__device__ __forceinline__ double warpMaxD(double v) {
    #pragma unroll
    for (int o = 16; o; o >>= 1) v = fmax(v, __shfl_xor_sync(0xffffffffu, v, o));
    return v;
}

struct RedShared {
    double d[16];
    unsigned long long u[8];
};

__device__ __forceinline__ double blockSumD(double v, RedShared* sh) {
    int lane = threadIdx.x & 31, w = threadIdx.x >> 5;
    v = warpSumT(v);
    if (lane == 0) sh->d[w] = v;
    __syncthreads();
    if (w == 0) {
        double t = (lane < 8) ? sh->d[lane] : 0.0;
        t = warpSumT(t);
        if (lane == 0) sh->d[0] = t;
    }
    __syncthreads();
    double r = sh->d[0];
    __syncthreads();
    return r;
}
__device__ __forceinline__ void blockSum2(double& a, double& b, RedShared* sh) {
    int lane = threadIdx.x & 31, w = threadIdx.x >> 5;
    a = warpSumT(a); b = warpSumT(b);
    if (lane == 0) { sh->d[w] = a; sh->d[8 + w] = b; }
    __syncthreads();
    if (w == 0) {
        double ta = (lane < 8) ? sh->d[lane] : 0.0;
        double tb = (lane < 8) ? sh->d[8 + lane] : 0.0;
        ta = warpSumT(ta); tb = warpSumT(tb);
        if (lane == 0) { sh->d[0] = ta; sh->d[8] = tb; }
    }
    __syncthreads();
    a = sh->d[0]; b = sh->d[8];
    __syncthreads();
}
__device__ __forceinline__ void blockSumU_MaxD(unsigned int& s, double& mx, RedShared* sh) {
    int lane = threadIdx.x & 31, w = threadIdx.x >> 5;
    s = warpSumT(s); mx = warpMaxD(mx);
    if (lane == 0) { sh->u[w] = s; sh->d[w] = mx; }
    __syncthreads();
    if (w == 0) {
        unsigned int ts = (lane < 8) ? (unsigned int)sh->u[lane] : 0u;
        double tm = (lane < 8) ? sh->d[lane] : -1e300;
        ts = warpSumT(ts); tm = warpMaxD(tm);
        if (lane == 0) { sh->u[0] = ts; sh->d[0] = tm; }
    }
    __syncthreads();
    s = (unsigned int)sh->u[0]; mx = sh->d[0];
    __syncthreads();
}
__device__ __forceinline__ unsigned int blockMaxU(unsigned int v, RedShared* sh) {
    int lane = threadIdx.x & 31, w = threadIdx.x >> 5;
    v = warpMaxU(v);
    if (lane == 0) sh->u[w] = v;
    __syncthreads();
    if (w == 0) {
        unsigned int t = (lane < 8) ? (unsigned int)sh->u[lane] : 0u;
        t = warpMaxU(t);
        if (lane == 0) sh->u[0] = t;
    }
    __syncthreads();
    unsigned int r = (unsigned int)sh->u[0];
    __syncthreads();
    return r;
}

// ---------------- per-candidate KL + fused argmin/reset ----------------
__global__ void kl_kernel(float* __restrict__ out) {
    const int i = IMIN + (int)blockIdx.x;
    const int L = 2 * i + 1;
    const int start = HALFB - i;
    const int stop = HALFB + i + 1;
    const int m = L / KQ;

    __shared__ unsigned int s_h[NBINS];
    __shared__ double s_q[KQ];
    __shared__ unsigned int s_nm[KQ];
    __shared__ RedShared s_red;

    for (int k = threadIdx.x; k < NBINS; k += 256) s_h[k] = g_hist[k];
    __syncthreads();

    const unsigned int left = g_csum[start];
    const unsigned int right = g_total - g_csum[stop];

    unsigned int pv[4], vv[4];
    unsigned int mpi = 0u;
    #pragma unroll
    for (int t = 0; t < 4; t++) {
        int k = threadIdx.x + t * 256;
        pv[t] = 0u; vv[t] = 0u;
        if (k < L) {
            unsigned int v = s_h[start + k];
            vv[t] = v;
            unsigned int p = v;
            if (k == 0) p += left;
            if (k == L - 1) p += right;
            pv[t] = p;
            mpi = max(mpi, p);
        }
    }
    mpi = blockMaxU(mpi, &s_red);
    const double mp = mpi ? (double)mpi : EPS_S;

    double qseg = 0.0;
    unsigned int nmj = 0u;
    if (threadIdx.x < KQ) {
        int j = threadIdx.x;
        int k0 = j * m;
        int k1 = (j == KQ - 1) ? L : (k0 + m);
        unsigned int sum = 0u, cnt = 0u;
        for (int k = k0; k < k1; k++) {
            unsigned int v = s_h[start + k];
            sum += v;
            cnt += (v != 0u && k != L - 1) ? 1u : 0u;
        }
        nmj = cnt;
        if (cnt > 0u) qseg = (double)sum / (double)cnt;
        s_q[j] = qseg;
        s_nm[j] = cnt;
    }
    unsigned int nnzq = nmj;
    double mq = (threadIdx.x < KQ && nmj > 0u) ? qseg : -1e300;
    blockSumU_MaxD(nnzq, mq, &s_red);
    mq = fmax(mq, EPS_S);

    double sq = 0.0;
    if (threadIdx.x < KQ && nmj > 0u) {
        double dq = qseg - mq;
        if (dq > EXP_CUT) sq = (double)nmj * exp(dq);
    }
    if (threadIdx.x == 0) {
        double dz = EPS_S - mq;
        if (dz > EXP_CUT) sq += (double)(L - (int)nnzq) * exp(dz);
    }
    double sp = 0.0;
    {
        double gate = mp + EXP_CUT;
        #pragma unroll
        for (int t = 0; t < 4; t++) {
            int k = threadIdx.x + t * 256;
            if (k < L) {
                double pl = pv[t] ? (double)pv[t] : EPS_S;
                if (pl > gate) sp += exp(pl - mp);
            }
        }
    }
    blockSum2(sp, sq, &s_red);
    const double lZp = mp + log(sp);
    const double lZq = mq + log(sq);

    double kl = 0.0;
    {
        double gate = lZp + EXP_CUT;
        #pragma unroll
        for (int t = 0; t < 4; t++) {
            int k = threadIdx.x + t * 256;
            if (k < L) {
                double pl = pv[t] ? (double)pv[t] : EPS_S;
                if (pl > gate) {
                    int seg = min(k / m, KQ - 1);
                    bool assigned = (vv[t] != 0u) && (k != L - 1) && (s_nm[seg] > 0u);
                    double ql = assigned ? s_q[seg] : EPS_S;
                    double lp = pl - lZp;
                    double lq = ql - lZq;
                    kl += exp(lp) * (lp - lq);
                }
            }
        }
    }
    kl = blockSumD(kl, &s_red);
    if (threadIdx.x == 0)
        g_kl[blockIdx.x] = (nnzq > 0u) ? kl : (double)INFINITY;

    // ---- fused argmin + output + global-state reset (last block) ----
    __shared__ unsigned int s_last;
    __threadfence();
    if (threadIdx.x == 0)
        s_last = (atomicAdd(&g_done2, 1u) == (unsigned int)(gridDim.x - 1)) ? 1u : 0u;
    __syncthreads();
    if (s_last) {
        __threadfence();
        __shared__ double sv[256];
        __shared__ int si[256];
        double best = (double)INFINITY;
        int bi = 0x7fffffff;
        for (int k = threadIdx.x; k < NCAND; k += 256) {
            double v = *(volatile double*)&g_kl[k];
            if (v < best || (v == best && k < bi)) { best = v; bi = k; }
        }
        sv[threadIdx.x] = best; si[threadIdx.x] = bi;
        __syncthreads();
        for (int s = 128; s > 0; s >>= 1) {
            if (threadIdx.x < s) {
                double vo = sv[threadIdx.x + s];
                int io = si[threadIdx.x + s];
                if (vo < sv[threadIdx.x] || (vo == sv[threadIdx.x] && io < si[threadIdx.x])) {
                    sv[threadIdx.x] = vo; si[threadIdx.x] = io;
                }
            }
            __syncthreads();
        }
        if (threadIdx.x == 0) {
            int ib = IMIN + si[0];
            float a = __uint_as_float(g_absmax_bits);
            double thr = -(double)a + 2.0 * (double)a * (double)(ib + HALFB + 1) / (double)NBINS;
            out[0] = (float)thr;
            // reset all global state for the next call/replay
            g_absmax_bits = 0u;
            g_bar = 0u;
            g_done = 0u;
            g_done2 = 0u;
        }
        for (int k = threadIdx.x; k < NBINS; k += 256) g_hist[k] = 0u;
    }
}

extern "C" void kernel_launch(void* const* d_in, const int* in_sizes, int n_in,
                              void* d_out, int out_size) {
    const float* x = (const float*)d_in[0];
    int n = in_sizes[0];
    main_kernel<<<MAIN_GRID, 256>>>(x, n);
    kl_kernel<<<NCAND, 256>>>((float*)d_out);
}